// round 12
// baseline (speedup 1.0000x reference)
#include <cuda_runtime.h>
#include <cstdint>

#define DSZ 64
#define N_SRC 50000
#define N_ALL 100000
#define E_ALL 1600000
#define TPB 256
#define WSTR 164     // packed weight row stride (8 og-blocks x 20 words + pad)
#define NTILE 128    // nodes per tile in final kernel (4 nodes per thread)
#define SSTR 66
#define NF_GRID 296

typedef unsigned long long f32x2_t;

__device__ __align__(16) float g_C[(size_t)N_ALL * DSZ];   // C[v] = sum norm*xs  (zeroed by node_final)
__device__ __align__(16) float g_c0[N_ALL];                // c0[v] = sum norm    (zeroed by node_final)
__device__ __align__(16) float g_Wp1[32 * WSTR];           // packed W1 d-pairs
__device__ __align__(16) float g_Wp2[32 * WSTR];           // packed W2 d-pairs

__device__ __forceinline__ f32x2_t ffma2(f32x2_t a, f32x2_t b, f32x2_t c) {
    f32x2_t d;
    asm("fma.rn.f32x2 %0, %1, %2, %3;" : "=l"(d) : "l"(a), "l"(b), "l"(c));
    return d;
}
__device__ __forceinline__ void unpack2(f32x2_t v, float& lo, float& hi) {
    unsigned a, b;
    asm("mov.b64 {%0, %1}, %2;" : "=r"(a), "=r"(b) : "l"(v));
    lo = __uint_as_float(a); hi = __uint_as_float(b);
}
__device__ __forceinline__ const float* node_ptr(const float* __restrict__ se,
                                                 const float* __restrict__ de,
                                                 int v) {
    return (v < N_SRC) ? se + (size_t)v * DSZ : de + (size_t)(v - N_SRC) * DSZ;
}

// ---------------- weight pack only (g_C/c0 zeroing is folded into node_final) ----------------
__global__ void prep_w_kernel(const float* __restrict__ W1,
                              const float* __restrict__ W2) {
    int i = blockIdx.x * blockDim.x + threadIdx.x;   // 4096
    int o = i >> 6, d = i & 63, dp = d >> 1;
    int idx = dp * WSTR + 20 * (o >> 3) + 2 * (o & 7) + (d & 1);
    g_Wp1[idx] = W1[i];
    g_Wp2[idx] = W2[i];
}

// ============ edge scatter: C[dst] += norm*xs ; c0[dst] += norm ============
__global__ __launch_bounds__(TPB)
void edge_scatter_kernel(const float* __restrict__ src_emb,
                         const float* __restrict__ dst_emb,
                         const float* __restrict__ norm,
                         const int* __restrict__ esrc,
                         const int* __restrict__ edst) {
    const int lane = threadIdx.x & 31;
    const int warp = (blockIdx.x * TPB + threadIdx.x) >> 5;
    const int nwarps = (gridDim.x * TPB) >> 5;
    const int half = lane >> 4;
    const int q    = lane & 15;

    for (int base = warp * 8; base < E_ALL; base += nwarps * 8) {
        int s[4], t[4]; float nv[4];
        #pragma unroll
        for (int j = 0; j < 4; j++) {
            int e = base + 2 * j + half;
            s[j]  = esrc[e];
            t[j]  = edst[e];
            nv[j] = norm[e];
        }
        float4 a[4];
        #pragma unroll
        for (int j = 0; j < 4; j++)
            a[j] = ((const float4*)node_ptr(src_emb, dst_emb, s[j]))[q];
        #pragma unroll
        for (int j = 0; j < 4; j++) {
            float cx = nv[j] * a[j].x, cy = nv[j] * a[j].y;
            float cz = nv[j] * a[j].z, cw = nv[j] * a[j].w;
            uintptr_t addr = (uintptr_t)&g_C[(size_t)t[j] * DSZ + 4 * q];
            asm volatile("red.global.add.v4.f32 [%0], {%1, %2, %3, %4};"
                         :: "l"(addr), "f"(cx), "f"(cy), "f"(cz), "f"(cw)
                         : "memory");
            if (q == 0) {
                uintptr_t a0 = (uintptr_t)&g_c0[t[j]];
                asm volatile("red.global.add.f32 [%0], %1;"
                             :: "l"(a0), "f"(nv[j]) : "memory");
            }
        }
    }
}

// ==== node final: out = lrelu(W1*C + W2*(x .* C) + c0*(b1+b2)); re-zeroes C/c0 ====
#define SMEM_W  (32 * WSTR)              // 5248 floats per matrix
#define SMEM_SP (NTILE * SSTR)           // 8448 floats per tile buffer
#define NF_SMEM ((2 * SMEM_W + 2 * SMEM_SP) * sizeof(float))   // 109568 B

__global__ __launch_bounds__(TPB, 2)
void node_final_kernel(const float* __restrict__ src_emb,
                       const float* __restrict__ dst_emb,
                       const float* __restrict__ b1,
                       const float* __restrict__ b2,
                       float* __restrict__ out) {
    extern __shared__ __align__(16) float dyn[];
    float* sW1 = dyn;                    // [32*WSTR]
    float* sW2 = dyn + SMEM_W;
    float* sp1 = dyn + 2 * SMEM_W;       // C rows      [NTILE*SSTR]
    float* sp2 = sp1 + SMEM_SP;          // x.*C rows

    const int tid = threadIdx.x, lane = tid & 31, w = tid >> 5;
    for (int i = tid; i < SMEM_W / 4; i += TPB) {
        ((float4*)sW1)[i] = ((const float4*)g_Wp1)[i];
        ((float4*)sW2)[i] = ((const float4*)g_Wp2)[i];
    }

    const int half = lane >> 4, q = lane & 15;      // phase A: warp stages 16 rows
    const int og = lane & 7, eg = lane >> 3;        // phase B
    const int nb = w * 16 + eg * 4;                 // 4 nodes per thread
    const int wb = 20 * og;

    float bias[8];
    {
        float4 u0 = *(const float4*)&b1[8 * og];
        float4 u1 = *(const float4*)&b1[8 * og + 4];
        float4 v0 = *(const float4*)&b2[8 * og];
        float4 v1 = *(const float4*)&b2[8 * og + 4];
        bias[0] = u0.x + v0.x; bias[1] = u0.y + v0.y;
        bias[2] = u0.z + v0.z; bias[3] = u0.w + v0.w;
        bias[4] = u1.x + v1.x; bias[5] = u1.y + v1.y;
        bias[6] = u1.z + v1.z; bias[7] = u1.w + v1.w;
    }
    __syncthreads();   // weights visible

    const int ntiles = (N_ALL + NTILE - 1) / NTILE;   // 782 (last partial: 32 rows)
    for (int tile = blockIdx.x; tile < ntiles; tile += gridDim.x) {
        const int base = tile * NTILE;
        // phase A: warp w stages rows [16w, 16w+16); zero-store consumed C
        #pragma unroll
        for (int j = 0; j < 8; j++) {
            int row = w * 16 + 2 * j + half;
            int v = base + row;
            float4 c4 = make_float4(0.f, 0.f, 0.f, 0.f);
            float4 x4 = make_float4(0.f, 0.f, 0.f, 0.f);
            if (v < N_ALL) {
                c4 = *(const float4*)&g_C[(size_t)v * DSZ + 4 * q];
                x4 = ((const float4*)node_ptr(src_emb, dst_emb, v))[q];
                *(float4*)&g_C[(size_t)v * DSZ + 4 * q] = make_float4(0.f, 0.f, 0.f, 0.f);
            }
            *(float2*)&sp1[row * SSTR + 4 * q]     = make_float2(c4.x, c4.y);
            *(float2*)&sp1[row * SSTR + 4 * q + 2] = make_float2(c4.z, c4.w);
            *(float2*)&sp2[row * SSTR + 4 * q]     = make_float2(x4.x * c4.x, x4.y * c4.y);
            *(float2*)&sp2[row * SSTR + 4 * q + 2] = make_float2(x4.z * c4.z, x4.w * c4.w);
        }
        __syncthreads();

        const int gvb = base + nb;
        const bool valid = (gvb < N_ALL);   // all-or-none per 4-node group
        float4 c0v = make_float4(0.f, 0.f, 0.f, 0.f);
        if (valid) {
            c0v = *(const float4*)&g_c0[gvb];
            if (og == 0)
                *(float4*)&g_c0[gvb] = make_float4(0.f, 0.f, 0.f, 0.f);
        }

        f32x2_t ac[4][8];
        #pragma unroll
        for (int k = 0; k < 4; k++)
            #pragma unroll
            for (int o = 0; o < 8; o++) ac[k][o] = 0;

        #pragma unroll 2
        for (int dp = 0; dp < 32; dp++) {
            const float* w1r = &sW1[dp * WSTR + wb];
            const float* w2r = &sW2[dp * WSTR + wb];
            ulonglong2 wA1 = *(const ulonglong2*)(w1r);
            ulonglong2 wB1 = *(const ulonglong2*)(w1r + 4);
            ulonglong2 wC1 = *(const ulonglong2*)(w1r + 8);
            ulonglong2 wD1 = *(const ulonglong2*)(w1r + 12);
            ulonglong2 wA2 = *(const ulonglong2*)(w2r);
            ulonglong2 wB2 = *(const ulonglong2*)(w2r + 4);
            ulonglong2 wC2 = *(const ulonglong2*)(w2r + 8);
            ulonglong2 wD2 = *(const ulonglong2*)(w2r + 12);
            #pragma unroll
            for (int k = 0; k < 4; k++) {
                const int pb = (nb + k) * SSTR;
                f32x2_t p1 = *(const f32x2_t*)&sp1[pb + 2 * dp];
                f32x2_t p2 = *(const f32x2_t*)&sp2[pb + 2 * dp];
                ac[k][0] = ffma2(p1, wA1.x, ac[k][0]);
                ac[k][1] = ffma2(p1, wA1.y, ac[k][1]);
                ac[k][2] = ffma2(p1, wB1.x, ac[k][2]);
                ac[k][3] = ffma2(p1, wB1.y, ac[k][3]);
                ac[k][4] = ffma2(p1, wC1.x, ac[k][4]);
                ac[k][5] = ffma2(p1, wC1.y, ac[k][5]);
                ac[k][6] = ffma2(p1, wD1.x, ac[k][6]);
                ac[k][7] = ffma2(p1, wD1.y, ac[k][7]);
                ac[k][0] = ffma2(p2, wA2.x, ac[k][0]);
                ac[k][1] = ffma2(p2, wA2.y, ac[k][1]);
                ac[k][2] = ffma2(p2, wB2.x, ac[k][2]);
                ac[k][3] = ffma2(p2, wB2.y, ac[k][3]);
                ac[k][4] = ffma2(p2, wC2.x, ac[k][4]);
                ac[k][5] = ffma2(p2, wC2.y, ac[k][5]);
                ac[k][6] = ffma2(p2, wD2.x, ac[k][6]);
                ac[k][7] = ffma2(p2, wD2.y, ac[k][7]);
            }
        }

        if (valid) {
            const float* c0p = (const float*)&c0v;
            #pragma unroll
            for (int k = 0; k < 4; k++) {
                float vv[8];
                #pragma unroll
                for (int o = 0; o < 8; o++) {
                    float lo, hi;
                    unpack2(ac[k][o], lo, hi);
                    float h = lo + hi + c0p[k] * bias[o];
                    vv[o] = h > 0.f ? h : 0.2f * h;
                }
                *(float4*)&out[(size_t)(gvb + k) * DSZ + 8 * og] =
                    make_float4(vv[0], vv[1], vv[2], vv[3]);
                *(float4*)&out[(size_t)(gvb + k) * DSZ + 8 * og + 4] =
                    make_float4(vv[4], vv[5], vv[6], vv[7]);
            }
        }
        __syncthreads();
    }
}

extern "C" void kernel_launch(void* const* d_in, const int* in_sizes, int n_in,
                              void* d_out, int out_size) {
    const float* src_emb = (const float*)d_in[0];
    const float* dst_emb = (const float*)d_in[1];
    const float* norm    = (const float*)d_in[2];
    const float* W1      = (const float*)d_in[3];
    const float* b1      = (const float*)d_in[4];
    const float* W2      = (const float*)d_in[5];
    const float* b2      = (const float*)d_in[6];
    const int*   esrc    = (const int*)d_in[7];
    const int*   edst    = (const int*)d_in[8];
    float* out = (float*)d_out;

    cudaFuncSetAttribute(node_final_kernel,
                         cudaFuncAttributeMaxDynamicSharedMemorySize, NF_SMEM);

    // g_C / g_c0 start zero (zero-initialized device globals on first call,
    // re-zeroed by node_final on every call) -> no zeroing pass needed.
    prep_w_kernel<<<16, 256>>>(W1, W2);
    edge_scatter_kernel<<<1184, TPB>>>(src_emb, dst_emb, norm, esrc, edst);
    node_final_kernel<<<NF_GRID, TPB, NF_SMEM>>>(src_emb, dst_emb, b1, b2, out);
}

// round 13
// speedup vs baseline: 1.1545x; 1.1545x over previous
#include <cuda_runtime.h>
#include <cstdint>

#define DSZ 64
#define N_SRC 50000
#define N_ALL 100000
#define E_ALL 1600000
#define TPB 256
#define WSTR 164     // packed weight row stride (8 og-blocks x 20 words + pad)
#define NTILE 64     // nodes per tile in final kernel (2 nodes per thread)
#define SSTR 66
#define NF_GRID 296

typedef unsigned long long f32x2_t;

__device__ __align__(16) float g_C[(size_t)N_ALL * DSZ];   // C[v] = sum norm*xs (re-zeroed each call)
__device__ __align__(16) float g_c0[N_ALL];                // c0[v] = sum norm   (re-zeroed each call)
__device__ __align__(16) float g_Wp1[32 * WSTR];           // packed W1 d-pairs
__device__ __align__(16) float g_Wp2[32 * WSTR];           // packed W2 d-pairs

__device__ __forceinline__ f32x2_t ffma2(f32x2_t a, f32x2_t b, f32x2_t c) {
    f32x2_t d;
    asm("fma.rn.f32x2 %0, %1, %2, %3;" : "=l"(d) : "l"(a), "l"(b), "l"(c));
    return d;
}
__device__ __forceinline__ void unpack2(f32x2_t v, float& lo, float& hi) {
    unsigned a, b;
    asm("mov.b64 {%0, %1}, %2;" : "=r"(a), "=r"(b) : "l"(v));
    lo = __uint_as_float(a); hi = __uint_as_float(b);
}
__device__ __forceinline__ const float* node_ptr(const float* __restrict__ se,
                                                 const float* __restrict__ de,
                                                 int v) {
    return (v < N_SRC) ? se + (size_t)v * DSZ : de + (size_t)(v - N_SRC) * DSZ;
}

// ---------------- weight pack only ----------------
__global__ void prep_w_kernel(const float* __restrict__ W1,
                              const float* __restrict__ W2) {
    int i = blockIdx.x * blockDim.x + threadIdx.x;   // 4096
    int o = i >> 6, d = i & 63, dp = d >> 1;
    int idx = dp * WSTR + 20 * (o >> 3) + 2 * (o & 7) + (d & 1);
    g_Wp1[idx] = W1[i];
    g_Wp2[idx] = W2[i];
}

// ============ edge scatter: C[dst] += norm*xs ; c0[dst] += norm ============
__global__ __launch_bounds__(TPB)
void edge_scatter_kernel(const float* __restrict__ src_emb,
                         const float* __restrict__ dst_emb,
                         const float* __restrict__ norm,
                         const int* __restrict__ esrc,
                         const int* __restrict__ edst) {
    const int lane = threadIdx.x & 31;
    const int warp = (blockIdx.x * TPB + threadIdx.x) >> 5;
    const int nwarps = (gridDim.x * TPB) >> 5;
    const int half = lane >> 4;
    const int q    = lane & 15;

    for (int base = warp * 8; base < E_ALL; base += nwarps * 8) {
        int s[4], t[4]; float nv[4];
        #pragma unroll
        for (int j = 0; j < 4; j++) {
            int e = base + 2 * j + half;
            s[j]  = esrc[e];
            t[j]  = edst[e];
            nv[j] = norm[e];
        }
        float4 a[4];
        #pragma unroll
        for (int j = 0; j < 4; j++)
            a[j] = ((const float4*)node_ptr(src_emb, dst_emb, s[j]))[q];
        #pragma unroll
        for (int j = 0; j < 4; j++) {
            float cx = nv[j] * a[j].x, cy = nv[j] * a[j].y;
            float cz = nv[j] * a[j].z, cw = nv[j] * a[j].w;
            uintptr_t addr = (uintptr_t)&g_C[(size_t)t[j] * DSZ + 4 * q];
            asm volatile("red.global.add.v4.f32 [%0], {%1, %2, %3, %4};"
                         :: "l"(addr), "f"(cx), "f"(cy), "f"(cz), "f"(cw)
                         : "memory");
            if (q == 0) {
                uintptr_t a0 = (uintptr_t)&g_c0[t[j]];
                asm volatile("red.global.add.f32 [%0], %1;"
                             :: "l"(a0), "f"(nv[j]) : "memory");
            }
        }
    }
}

// ==== node final: out = lrelu(W1*C + W2*(x .* C) + c0*(b1+b2)); re-zeroes C/c0 ====
#define SMEM_W  (32 * WSTR)              // 5248 floats per matrix
#define SMEM_SP (NTILE * SSTR)           // 4224 floats per tile buffer
#define NF_SMEM ((2 * SMEM_W + 2 * SMEM_SP) * sizeof(float))   // 75776 B

__global__ __launch_bounds__(TPB, 2)
void node_final_kernel(const float* __restrict__ src_emb,
                       const float* __restrict__ dst_emb,
                       const float* __restrict__ b1,
                       const float* __restrict__ b2,
                       float* __restrict__ out) {
    extern __shared__ __align__(16) float dyn[];
    float* sW1 = dyn;                    // [32*WSTR]
    float* sW2 = dyn + SMEM_W;
    float* sp1 = dyn + 2 * SMEM_W;       // C rows      [NTILE*SSTR]
    float* sp2 = sp1 + SMEM_SP;          // x.*C rows

    const int tid = threadIdx.x, lane = tid & 31, w = tid >> 5;
    for (int i = tid; i < SMEM_W / 4; i += TPB) {
        ((float4*)sW1)[i] = ((const float4*)g_Wp1)[i];
        ((float4*)sW2)[i] = ((const float4*)g_Wp2)[i];
    }

    const int half = lane >> 4, q = lane & 15;      // phase A: warp stages 8 rows
    const int og = lane & 7, eg = lane >> 3;        // phase B
    const int n0 = w * 8 + eg * 2, n1 = n0 + 1;     // 2 nodes per thread
    const int wb = 20 * og;
    const int pb0 = n0 * SSTR, pb1 = n1 * SSTR;

    float bias[8];
    {
        float4 u0 = *(const float4*)&b1[8 * og];
        float4 u1 = *(const float4*)&b1[8 * og + 4];
        float4 v0 = *(const float4*)&b2[8 * og];
        float4 v1 = *(const float4*)&b2[8 * og + 4];
        bias[0] = u0.x + v0.x; bias[1] = u0.y + v0.y;
        bias[2] = u0.z + v0.z; bias[3] = u0.w + v0.w;
        bias[4] = u1.x + v1.x; bias[5] = u1.y + v1.y;
        bias[6] = u1.z + v1.z; bias[7] = u1.w + v1.w;
    }
    __syncthreads();   // weights visible

    const int ntiles = (N_ALL + NTILE - 1) / NTILE;   // 1563 (last partial)

    // prefetch first tile's C and x rows into registers
    float4 cpre[4], xpre[4];
    int tile = blockIdx.x;
    if (tile < ntiles) {
        #pragma unroll
        for (int j = 0; j < 4; j++) {
            int v = tile * NTILE + w * 8 + 2 * j + half;
            if (v < N_ALL) {
                cpre[j] = *(const float4*)&g_C[(size_t)v * DSZ + 4 * q];
                xpre[j] = ((const float4*)node_ptr(src_emb, dst_emb, v))[q];
            } else {
                cpre[j] = make_float4(0.f, 0.f, 0.f, 0.f);
                xpre[j] = make_float4(0.f, 0.f, 0.f, 0.f);
            }
        }
    }

    for (; tile < ntiles; tile += gridDim.x) {
        const int base = tile * NTILE;
        // phase A: store prefetched rows to smem; zero-store consumed C
        #pragma unroll
        for (int j = 0; j < 4; j++) {
            int row = w * 8 + 2 * j + half;
            int v = base + row;
            float4 c4 = cpre[j], x4 = xpre[j];
            if (v < N_ALL)
                *(float4*)&g_C[(size_t)v * DSZ + 4 * q] = make_float4(0.f, 0.f, 0.f, 0.f);
            *(float2*)&sp1[row * SSTR + 4 * q]     = make_float2(c4.x, c4.y);
            *(float2*)&sp1[row * SSTR + 4 * q + 2] = make_float2(c4.z, c4.w);
            *(float2*)&sp2[row * SSTR + 4 * q]     = make_float2(x4.x * c4.x, x4.y * c4.y);
            *(float2*)&sp2[row * SSTR + 4 * q + 2] = make_float2(x4.z * c4.z, x4.w * c4.w);
        }
        __syncthreads();

        // prefetch NEXT tile's rows (overlaps the GEMM below)
        int nt = tile + gridDim.x;
        if (nt < ntiles) {
            #pragma unroll
            for (int j = 0; j < 4; j++) {
                int v = nt * NTILE + w * 8 + 2 * j + half;
                if (v < N_ALL) {
                    cpre[j] = *(const float4*)&g_C[(size_t)v * DSZ + 4 * q];
                    xpre[j] = ((const float4*)node_ptr(src_emb, dst_emb, v))[q];
                } else {
                    cpre[j] = make_float4(0.f, 0.f, 0.f, 0.f);
                    xpre[j] = make_float4(0.f, 0.f, 0.f, 0.f);
                }
            }
        }

        const int gv0 = base + n0, gv1 = base + n1;
        const float c00 = (gv0 < N_ALL) ? g_c0[gv0] : 0.f;
        const float c01 = (gv1 < N_ALL) ? g_c0[gv1] : 0.f;
        if (og == 0 && gv0 < N_ALL)   // n0 even, n1 = n0+1 -> one float2 zero
            *(float2*)&g_c0[gv0] = make_float2(0.f, 0.f);

        f32x2_t ac0[8], ac1[8];
        #pragma unroll
        for (int o = 0; o < 8; o++) { ac0[o] = 0; ac1[o] = 0; }
        #pragma unroll 4
        for (int dp = 0; dp < 32; dp++) {
            f32x2_t p1a = *(const f32x2_t*)&sp1[pb0 + 2 * dp];
            f32x2_t p2a = *(const f32x2_t*)&sp2[pb0 + 2 * dp];
            f32x2_t p1b = *(const f32x2_t*)&sp1[pb1 + 2 * dp];
            f32x2_t p2b = *(const f32x2_t*)&sp2[pb1 + 2 * dp];
            const float* w1r = &sW1[dp * WSTR + wb];
            const float* w2r = &sW2[dp * WSTR + wb];
            ulonglong2 wA = *(const ulonglong2*)(w1r);
            ulonglong2 wB = *(const ulonglong2*)(w1r + 4);
            ulonglong2 wC = *(const ulonglong2*)(w1r + 8);
            ulonglong2 wD = *(const ulonglong2*)(w1r + 12);
            ac0[0] = ffma2(p1a, wA.x, ac0[0]); ac1[0] = ffma2(p1b, wA.x, ac1[0]);
            ac0[1] = ffma2(p1a, wA.y, ac0[1]); ac1[1] = ffma2(p1b, wA.y, ac1[1]);
            ac0[2] = ffma2(p1a, wB.x, ac0[2]); ac1[2] = ffma2(p1b, wB.x, ac1[2]);
            ac0[3] = ffma2(p1a, wB.y, ac0[3]); ac1[3] = ffma2(p1b, wB.y, ac1[3]);
            ac0[4] = ffma2(p1a, wC.x, ac0[4]); ac1[4] = ffma2(p1b, wC.x, ac1[4]);
            ac0[5] = ffma2(p1a, wC.y, ac0[5]); ac1[5] = ffma2(p1b, wC.y, ac1[5]);
            ac0[6] = ffma2(p1a, wD.x, ac0[6]); ac1[6] = ffma2(p1b, wD.x, ac1[6]);
            ac0[7] = ffma2(p1a, wD.y, ac0[7]); ac1[7] = ffma2(p1b, wD.y, ac1[7]);
            wA = *(const ulonglong2*)(w2r);
            wB = *(const ulonglong2*)(w2r + 4);
            wC = *(const ulonglong2*)(w2r + 8);
            wD = *(const ulonglong2*)(w2r + 12);
            ac0[0] = ffma2(p2a, wA.x, ac0[0]); ac1[0] = ffma2(p2b, wA.x, ac1[0]);
            ac0[1] = ffma2(p2a, wA.y, ac0[1]); ac1[1] = ffma2(p2b, wA.y, ac1[1]);
            ac0[2] = ffma2(p2a, wB.x, ac0[2]); ac1[2] = ffma2(p2b, wB.x, ac1[2]);
            ac0[3] = ffma2(p2a, wB.y, ac0[3]); ac1[3] = ffma2(p2b, wB.y, ac1[3]);
            ac0[4] = ffma2(p2a, wC.x, ac0[4]); ac1[4] = ffma2(p2b, wC.x, ac1[4]);
            ac0[5] = ffma2(p2a, wC.y, ac0[5]); ac1[5] = ffma2(p2b, wC.y, ac1[5]);
            ac0[6] = ffma2(p2a, wD.x, ac0[6]); ac1[6] = ffma2(p2b, wD.x, ac1[6]);
            ac0[7] = ffma2(p2a, wD.y, ac0[7]); ac1[7] = ffma2(p2b, wD.y, ac1[7]);
        }
        float va[8], vb[8];
        #pragma unroll
        for (int o = 0; o < 8; o++) {
            float lo, hi;
            unpack2(ac0[o], lo, hi);
            float h = lo + hi + c00 * bias[o];
            va[o] = h > 0.f ? h : 0.2f * h;
            unpack2(ac1[o], lo, hi);
            h = lo + hi + c01 * bias[o];
            vb[o] = h > 0.f ? h : 0.2f * h;
        }
        if (gv0 < N_ALL) {
            *(float4*)&out[(size_t)gv0 * DSZ + 8 * og]     = make_float4(va[0], va[1], va[2], va[3]);
            *(float4*)&out[(size_t)gv0 * DSZ + 8 * og + 4] = make_float4(va[4], va[5], va[6], va[7]);
        }
        if (gv1 < N_ALL) {
            *(float4*)&out[(size_t)gv1 * DSZ + 8 * og]     = make_float4(vb[0], vb[1], vb[2], vb[3]);
            *(float4*)&out[(size_t)gv1 * DSZ + 8 * og + 4] = make_float4(vb[4], vb[5], vb[6], vb[7]);
        }
        __syncthreads();
    }
}

extern "C" void kernel_launch(void* const* d_in, const int* in_sizes, int n_in,
                              void* d_out, int out_size) {
    const float* src_emb = (const float*)d_in[0];
    const float* dst_emb = (const float*)d_in[1];
    const float* norm    = (const float*)d_in[2];
    const float* W1      = (const float*)d_in[3];
    const float* b1      = (const float*)d_in[4];
    const float* W2      = (const float*)d_in[5];
    const float* b2      = (const float*)d_in[6];
    const int*   esrc    = (const int*)d_in[7];
    const int*   edst    = (const int*)d_in[8];
    float* out = (float*)d_out;

    cudaFuncSetAttribute(node_final_kernel,
                         cudaFuncAttributeMaxDynamicSharedMemorySize, NF_SMEM);

    // g_C / g_c0 are zero-initialized device globals; node_final re-zeroes
    // them every call -> no separate zeroing pass.
    prep_w_kernel<<<16, 256>>>(W1, W2);
    edge_scatter_kernel<<<1184, TPB>>>(src_emb, dst_emb, norm, esrc, edst);
    node_final_kernel<<<NF_GRID, TPB, NF_SMEM>>>(src_emb, dst_emb, b1, b2, out);
}

// round 14
// speedup vs baseline: 1.1557x; 1.0010x over previous
#include <cuda_runtime.h>
#include <cstdint>

#define DSZ 64
#define N_SRC 50000
#define N_ALL 100000
#define E_ALL 1600000
#define TPB 256
#define WSTR 164     // packed weight row stride (8 og-blocks x 20 words + pad)
#define NTILE 64     // nodes per tile in final kernel (2 nodes per thread)
#define SSTR 66
#define NF_GRID 296

typedef unsigned long long f32x2_t;

__device__ __align__(16) float g_C[(size_t)N_ALL * DSZ];   // C[v] = sum norm*xs (re-zeroed each call)
__device__ __align__(16) float g_c0[N_ALL];                // c0[v] = sum norm   (re-zeroed each call)
__device__ __align__(16) float g_Wp1[32 * WSTR];           // packed W1 d-pairs
__device__ __align__(16) float g_Wp2[32 * WSTR];           // packed W2 d-pairs

__device__ __forceinline__ f32x2_t ffma2(f32x2_t a, f32x2_t b, f32x2_t c) {
    f32x2_t d;
    asm("fma.rn.f32x2 %0, %1, %2, %3;" : "=l"(d) : "l"(a), "l"(b), "l"(c));
    return d;
}
__device__ __forceinline__ void unpack2(f32x2_t v, float& lo, float& hi) {
    unsigned a, b;
    asm("mov.b64 {%0, %1}, %2;" : "=r"(a), "=r"(b) : "l"(v));
    lo = __uint_as_float(a); hi = __uint_as_float(b);
}
__device__ __forceinline__ const float* node_ptr(const float* __restrict__ se,
                                                 const float* __restrict__ de,
                                                 int v) {
    return (v < N_SRC) ? se + (size_t)v * DSZ : de + (size_t)(v - N_SRC) * DSZ;
}

// ============ edge scatter (+ weight pack in first 16 CTAs) ============
// Ordering: node_final (next launch) is the only consumer of g_Wp1/g_Wp2;
// the kernel boundary orders the packing stores before node_final's loads.
__global__ __launch_bounds__(TPB)
void edge_scatter_kernel(const float* __restrict__ src_emb,
                         const float* __restrict__ dst_emb,
                         const float* __restrict__ norm,
                         const int* __restrict__ esrc,
                         const int* __restrict__ edst,
                         const float* __restrict__ W1,
                         const float* __restrict__ W2) {
    if (blockIdx.x < 16) {
        int i = blockIdx.x * TPB + threadIdx.x;   // 4096 threads cover W
        int o = i >> 6, d = i & 63, dp = d >> 1;
        int idx = dp * WSTR + 20 * (o >> 3) + 2 * (o & 7) + (d & 1);
        g_Wp1[idx] = W1[i];
        g_Wp2[idx] = W2[i];
    }

    const int lane = threadIdx.x & 31;
    const int warp = (blockIdx.x * TPB + threadIdx.x) >> 5;
    const int nwarps = (gridDim.x * TPB) >> 5;
    const int half = lane >> 4;
    const int q    = lane & 15;

    for (int base = warp * 8; base < E_ALL; base += nwarps * 8) {
        int s[4], t[4]; float nv[4];
        #pragma unroll
        for (int j = 0; j < 4; j++) {
            int e = base + 2 * j + half;
            s[j]  = esrc[e];
            t[j]  = edst[e];
            nv[j] = norm[e];
        }
        float4 a[4];
        #pragma unroll
        for (int j = 0; j < 4; j++)
            a[j] = ((const float4*)node_ptr(src_emb, dst_emb, s[j]))[q];
        #pragma unroll
        for (int j = 0; j < 4; j++) {
            float cx = nv[j] * a[j].x, cy = nv[j] * a[j].y;
            float cz = nv[j] * a[j].z, cw = nv[j] * a[j].w;
            uintptr_t addr = (uintptr_t)&g_C[(size_t)t[j] * DSZ + 4 * q];
            asm volatile("red.global.add.v4.f32 [%0], {%1, %2, %3, %4};"
                         :: "l"(addr), "f"(cx), "f"(cy), "f"(cz), "f"(cw)
                         : "memory");
            if (q == 0) {
                uintptr_t a0 = (uintptr_t)&g_c0[t[j]];
                asm volatile("red.global.add.f32 [%0], %1;"
                             :: "l"(a0), "f"(nv[j]) : "memory");
            }
        }
    }
}

// ==== node final: out = lrelu(W1*C + W2*(x .* C) + c0*(b1+b2)); re-zeroes C/c0 ====
#define SMEM_W  (32 * WSTR)              // 5248 floats per matrix
#define SMEM_SP (NTILE * SSTR)           // 4224 floats per tile buffer
#define NF_SMEM ((2 * SMEM_W + 2 * SMEM_SP) * sizeof(float))   // 75776 B

__global__ __launch_bounds__(TPB, 2)
void node_final_kernel(const float* __restrict__ src_emb,
                       const float* __restrict__ dst_emb,
                       const float* __restrict__ b1,
                       const float* __restrict__ b2,
                       float* __restrict__ out) {
    extern __shared__ __align__(16) float dyn[];
    float* sW1 = dyn;                    // [32*WSTR]
    float* sW2 = dyn + SMEM_W;
    float* sp1 = dyn + 2 * SMEM_W;       // C rows      [NTILE*SSTR]
    float* sp2 = sp1 + SMEM_SP;          // x.*C rows

    const int tid = threadIdx.x, lane = tid & 31, w = tid >> 5;
    for (int i = tid; i < SMEM_W / 4; i += TPB) {
        ((float4*)sW1)[i] = ((const float4*)g_Wp1)[i];
        ((float4*)sW2)[i] = ((const float4*)g_Wp2)[i];
    }

    const int half = lane >> 4, q = lane & 15;      // phase A: warp stages 8 rows
    const int og = lane & 7, eg = lane >> 3;        // phase B
    const int n0 = w * 8 + eg * 2, n1 = n0 + 1;     // 2 nodes per thread
    const int wb = 20 * og;
    const int pb0 = n0 * SSTR, pb1 = n1 * SSTR;

    float bias[8];
    {
        float4 u0 = *(const float4*)&b1[8 * og];
        float4 u1 = *(const float4*)&b1[8 * og + 4];
        float4 v0 = *(const float4*)&b2[8 * og];
        float4 v1 = *(const float4*)&b2[8 * og + 4];
        bias[0] = u0.x + v0.x; bias[1] = u0.y + v0.y;
        bias[2] = u0.z + v0.z; bias[3] = u0.w + v0.w;
        bias[4] = u1.x + v1.x; bias[5] = u1.y + v1.y;
        bias[6] = u1.z + v1.z; bias[7] = u1.w + v1.w;
    }
    __syncthreads();   // weights visible

    const int ntiles = (N_ALL + NTILE - 1) / NTILE;   // 1563 (last partial)

    float4 cpre[4], xpre[4];
    int tile = blockIdx.x;
    if (tile < ntiles) {
        #pragma unroll
        for (int j = 0; j < 4; j++) {
            int v = tile * NTILE + w * 8 + 2 * j + half;
            if (v < N_ALL) {
                cpre[j] = *(const float4*)&g_C[(size_t)v * DSZ + 4 * q];
                xpre[j] = ((const float4*)node_ptr(src_emb, dst_emb, v))[q];
            } else {
                cpre[j] = make_float4(0.f, 0.f, 0.f, 0.f);
                xpre[j] = make_float4(0.f, 0.f, 0.f, 0.f);
            }
        }
    }

    for (; tile < ntiles; tile += gridDim.x) {
        const int base = tile * NTILE;
        // phase A: store prefetched rows; zero-store consumed C
        #pragma unroll
        for (int j = 0; j < 4; j++) {
            int row = w * 8 + 2 * j + half;
            int v = base + row;
            float4 c4 = cpre[j], x4 = xpre[j];
            if (v < N_ALL)
                *(float4*)&g_C[(size_t)v * DSZ + 4 * q] = make_float4(0.f, 0.f, 0.f, 0.f);
            *(float2*)&sp1[row * SSTR + 4 * q]     = make_float2(c4.x, c4.y);
            *(float2*)&sp1[row * SSTR + 4 * q + 2] = make_float2(c4.z, c4.w);
            *(float2*)&sp2[row * SSTR + 4 * q]     = make_float2(x4.x * c4.x, x4.y * c4.y);
            *(float2*)&sp2[row * SSTR + 4 * q + 2] = make_float2(x4.z * c4.z, x4.w * c4.w);
        }
        __syncthreads();

        // prefetch NEXT tile's rows (overlaps the GEMM below)
        int nt = tile + gridDim.x;
        if (nt < ntiles) {
            #pragma unroll
            for (int j = 0; j < 4; j++) {
                int v = nt * NTILE + w * 8 + 2 * j + half;
                if (v < N_ALL) {
                    cpre[j] = *(const float4*)&g_C[(size_t)v * DSZ + 4 * q];
                    xpre[j] = ((const float4*)node_ptr(src_emb, dst_emb, v))[q];
                } else {
                    cpre[j] = make_float4(0.f, 0.f, 0.f, 0.f);
                    xpre[j] = make_float4(0.f, 0.f, 0.f, 0.f);
                }
            }
        }

        const int gv0 = base + n0, gv1 = base + n1;
        const float c00 = (gv0 < N_ALL) ? g_c0[gv0] : 0.f;
        const float c01 = (gv1 < N_ALL) ? g_c0[gv1] : 0.f;
        if (og == 0 && gv0 < N_ALL)
            *(float2*)&g_c0[gv0] = make_float2(0.f, 0.f);

        f32x2_t ac0[8], ac1[8];
        #pragma unroll
        for (int o = 0; o < 8; o++) { ac0[o] = 0; ac1[o] = 0; }
        #pragma unroll 8
        for (int dp = 0; dp < 32; dp++) {
            f32x2_t p1a = *(const f32x2_t*)&sp1[pb0 + 2 * dp];
            f32x2_t p2a = *(const f32x2_t*)&sp2[pb0 + 2 * dp];
            f32x2_t p1b = *(const f32x2_t*)&sp1[pb1 + 2 * dp];
            f32x2_t p2b = *(const f32x2_t*)&sp2[pb1 + 2 * dp];
            const float* w1r = &sW1[dp * WSTR + wb];
            const float* w2r = &sW2[dp * WSTR + wb];
            ulonglong2 wA = *(const ulonglong2*)(w1r);
            ulonglong2 wB = *(const ulonglong2*)(w1r + 4);
            ulonglong2 wC = *(const ulonglong2*)(w1r + 8);
            ulonglong2 wD = *(const ulonglong2*)(w1r + 12);
            ac0[0] = ffma2(p1a, wA.x, ac0[0]); ac1[0] = ffma2(p1b, wA.x, ac1[0]);
            ac0[1] = ffma2(p1a, wA.y, ac0[1]); ac1[1] = ffma2(p1b, wA.y, ac1[1]);
            ac0[2] = ffma2(p1a, wB.x, ac0[2]); ac1[2] = ffma2(p1b, wB.x, ac1[2]);
            ac0[3] = ffma2(p1a, wB.y, ac0[3]); ac1[3] = ffma2(p1b, wB.y, ac1[3]);
            ac0[4] = ffma2(p1a, wC.x, ac0[4]); ac1[4] = ffma2(p1b, wC.x, ac1[4]);
            ac0[5] = ffma2(p1a, wC.y, ac0[5]); ac1[5] = ffma2(p1b, wC.y, ac1[5]);
            ac0[6] = ffma2(p1a, wD.x, ac0[6]); ac1[6] = ffma2(p1b, wD.x, ac1[6]);
            ac0[7] = ffma2(p1a, wD.y, ac0[7]); ac1[7] = ffma2(p1b, wD.y, ac1[7]);
            wA = *(const ulonglong2*)(w2r);
            wB = *(const ulonglong2*)(w2r + 4);
            wC = *(const ulonglong2*)(w2r + 8);
            wD = *(const ulonglong2*)(w2r + 12);
            ac0[0] = ffma2(p2a, wA.x, ac0[0]); ac1[0] = ffma2(p2b, wA.x, ac1[0]);
            ac0[1] = ffma2(p2a, wA.y, ac0[1]); ac1[1] = ffma2(p2b, wA.y, ac1[1]);
            ac0[2] = ffma2(p2a, wB.x, ac0[2]); ac1[2] = ffma2(p2b, wB.x, ac1[2]);
            ac0[3] = ffma2(p2a, wB.y, ac0[3]); ac1[3] = ffma2(p2b, wB.y, ac1[3]);
            ac0[4] = ffma2(p2a, wC.x, ac0[4]); ac1[4] = ffma2(p2b, wC.x, ac1[4]);
            ac0[5] = ffma2(p2a, wC.y, ac0[5]); ac1[5] = ffma2(p2b, wC.y, ac1[5]);
            ac0[6] = ffma2(p2a, wD.x, ac0[6]); ac1[6] = ffma2(p2b, wD.x, ac1[6]);
            ac0[7] = ffma2(p2a, wD.y, ac0[7]); ac1[7] = ffma2(p2b, wD.y, ac1[7]);
        }
        float va[8], vb[8];
        #pragma unroll
        for (int o = 0; o < 8; o++) {
            float lo, hi;
            unpack2(ac0[o], lo, hi);
            float h = lo + hi + c00 * bias[o];
            va[o] = h > 0.f ? h : 0.2f * h;
            unpack2(ac1[o], lo, hi);
            h = lo + hi + c01 * bias[o];
            vb[o] = h > 0.f ? h : 0.2f * h;
        }
        if (gv0 < N_ALL) {
            *(float4*)&out[(size_t)gv0 * DSZ + 8 * og]     = make_float4(va[0], va[1], va[2], va[3]);
            *(float4*)&out[(size_t)gv0 * DSZ + 8 * og + 4] = make_float4(va[4], va[5], va[6], va[7]);
        }
        if (gv1 < N_ALL) {
            *(float4*)&out[(size_t)gv1 * DSZ + 8 * og]     = make_float4(vb[0], vb[1], vb[2], vb[3]);
            *(float4*)&out[(size_t)gv1 * DSZ + 8 * og + 4] = make_float4(vb[4], vb[5], vb[6], vb[7]);
        }
        __syncthreads();
    }
}

extern "C" void kernel_launch(void* const* d_in, const int* in_sizes, int n_in,
                              void* d_out, int out_size) {
    const float* src_emb = (const float*)d_in[0];
    const float* dst_emb = (const float*)d_in[1];
    const float* norm    = (const float*)d_in[2];
    const float* W1      = (const float*)d_in[3];
    const float* b1      = (const float*)d_in[4];
    const float* W2      = (const float*)d_in[5];
    const float* b2      = (const float*)d_in[6];
    const int*   esrc    = (const int*)d_in[7];
    const int*   edst    = (const int*)d_in[8];
    float* out = (float*)d_out;

    cudaFuncSetAttribute(node_final_kernel,
                         cudaFuncAttributeMaxDynamicSharedMemorySize, NF_SMEM);

    // g_C / g_c0 are zero-initialized device globals; node_final re-zeroes
    // them every call -> no separate zeroing pass.
    edge_scatter_kernel<<<1184, TPB>>>(src_emb, dst_emb, norm, esrc, edst, W1, W2);
    node_final_kernel<<<NF_GRID, TPB, NF_SMEM>>>(src_emb, dst_emb, b1, b2, out);
}

// round 17
// speedup vs baseline: 1.2546x; 1.0855x over previous
#include <cuda_runtime.h>
#include <cstdint>

#define DSZ 64
#define N_SRC 50000
#define N_ALL 100000
#define E_ALL 1600000
#define TPB 256
#define WSTR 128     // packed weight row stride: 2 words x 64 outputs per dp
#define NTILE 64     // nodes per tile in final kernel (2 nodes per thread: lane, lane+32)
#define SSTR 66
#define NF_GRID 296

typedef unsigned long long f32x2_t;

__device__ __align__(16) float g_C[(size_t)N_ALL * DSZ];   // C[v] = sum norm*xs (re-zeroed each call)
__device__ __align__(16) float g_c0[N_ALL];                // c0[v] = sum norm   (re-zeroed each call)
__device__ __align__(16) float g_Wp1[32 * WSTR];           // packed W1 d-pairs: [dp][2o+(d&1)]
__device__ __align__(16) float g_Wp2[32 * WSTR];

__device__ __forceinline__ f32x2_t ffma2(f32x2_t a, f32x2_t b, f32x2_t c) {
    f32x2_t d;
    asm("fma.rn.f32x2 %0, %1, %2, %3;" : "=l"(d) : "l"(a), "l"(b), "l"(c));
    return d;
}
__device__ __forceinline__ void unpack2(f32x2_t v, float& lo, float& hi) {
    unsigned a, b;
    asm("mov.b64 {%0, %1}, %2;" : "=r"(a), "=r"(b) : "l"(v));
    lo = __uint_as_float(a); hi = __uint_as_float(b);
}
__device__ __forceinline__ const float* node_ptr(const float* __restrict__ se,
                                                 const float* __restrict__ de,
                                                 int v) {
    return (v < N_SRC) ? se + (size_t)v * DSZ : de + (size_t)(v - N_SRC) * DSZ;
}

// ============ edge scatter (+ weight pack in first 16 CTAs) ============
__global__ __launch_bounds__(TPB)
void edge_scatter_kernel(const float* __restrict__ src_emb,
                         const float* __restrict__ dst_emb,
                         const float* __restrict__ norm,
                         const int* __restrict__ esrc,
                         const int* __restrict__ edst,
                         const float* __restrict__ W1,
                         const float* __restrict__ W2) {
    if (blockIdx.x < 16) {
        int i = blockIdx.x * TPB + threadIdx.x;   // 4096 threads cover W
        int o = i >> 6, d = i & 63, dp = d >> 1;
        int idx = dp * WSTR + 2 * o + (d & 1);    // max 31*128+127 = 4095 < 4096
        g_Wp1[idx] = W1[i];
        g_Wp2[idx] = W2[i];
    }

    const int lane = threadIdx.x & 31;
    const int warp = (blockIdx.x * TPB + threadIdx.x) >> 5;
    const int nwarps = (gridDim.x * TPB) >> 5;
    const int half = lane >> 4;
    const int q    = lane & 15;

    for (int base = warp * 8; base < E_ALL; base += nwarps * 8) {
        int s[4], t[4]; float nv[4];
        #pragma unroll
        for (int j = 0; j < 4; j++) {
            int e = base + 2 * j + half;
            s[j]  = esrc[e];
            t[j]  = edst[e];
            nv[j] = norm[e];
        }
        float4 a[4];
        #pragma unroll
        for (int j = 0; j < 4; j++)
            a[j] = ((const float4*)node_ptr(src_emb, dst_emb, s[j]))[q];
        #pragma unroll
        for (int j = 0; j < 4; j++) {
            float cx = nv[j] * a[j].x, cy = nv[j] * a[j].y;
            float cz = nv[j] * a[j].z, cw = nv[j] * a[j].w;
            uintptr_t addr = (uintptr_t)&g_C[(size_t)t[j] * DSZ + 4 * q];
            asm volatile("red.global.add.v4.f32 [%0], {%1, %2, %3, %4};"
                         :: "l"(addr), "f"(cx), "f"(cy), "f"(cz), "f"(cw)
                         : "memory");
            if (q == 0) {
                uintptr_t a0 = (uintptr_t)&g_c0[t[j]];
                asm volatile("red.global.add.f32 [%0], %1;"
                             :: "l"(a0), "f"(nv[j]) : "memory");
            }
        }
    }
}

// ==== node final: out = lrelu(W1*C + W2*(x .* C) + c0*(b1+b2)); re-zeroes C/c0 ====
// Phase B: warp w -> outputs [8w,8w+8) (weight LDS = warp broadcast),
// lane l -> nodes l and l+32. p rows xor-swizzled (word = d ^ (row&16)).
// c0 zeroed after the end-of-tile barrier (all warps read the same 64 values).
#define SMEM_W  (32 * WSTR)              // 4096 floats per matrix (16 KB)
#define SMEM_SP (NTILE * SSTR)           // 4224 floats per tile buffer
#define NF_SMEM ((2 * SMEM_W + 2 * SMEM_SP) * sizeof(float))   // 66560 B

__global__ __launch_bounds__(TPB, 2)
void node_final_kernel(const float* __restrict__ src_emb,
                       const float* __restrict__ dst_emb,
                       const float* __restrict__ b1,
                       const float* __restrict__ b2,
                       float* __restrict__ out) {
    extern __shared__ __align__(16) float dyn[];
    float* sW1 = dyn;                    // [32*WSTR]
    float* sW2 = dyn + SMEM_W;
    float* sp1 = dyn + 2 * SMEM_W;       // C rows      [NTILE*SSTR], xor-swizzled
    float* sp2 = sp1 + SMEM_SP;          // x.*C rows

    const int tid = threadIdx.x, lane = tid & 31, w = tid >> 5;
    for (int i = tid; i < SMEM_W / 4; i += TPB) {
        ((float4*)sW1)[i] = ((const float4*)g_Wp1)[i];
        ((float4*)sW2)[i] = ((const float4*)g_Wp2)[i];
    }

    const int half = lane >> 4, q = lane & 15;      // phase A mapping
    const int sA = (lane & 16);                     // phase B p-swizzle bit
    const int pbA = lane * SSTR;                    // node lane
    const int pbB = (lane + 32) * SSTR;             // node lane+32 (same &16 bit)
    const int wbase = 16 * w;                       // weight word base for warp's 8 outputs

    float bias[8];
    {
        float4 u0 = *(const float4*)&b1[8 * w];
        float4 u1 = *(const float4*)&b1[8 * w + 4];
        float4 v0 = *(const float4*)&b2[8 * w];
        float4 v1 = *(const float4*)&b2[8 * w + 4];
        bias[0] = u0.x + v0.x; bias[1] = u0.y + v0.y;
        bias[2] = u0.z + v0.z; bias[3] = u0.w + v0.w;
        bias[4] = u1.x + v1.x; bias[5] = u1.y + v1.y;
        bias[6] = u1.z + v1.z; bias[7] = u1.w + v1.w;
    }
    __syncthreads();   // weights visible

    const int ntiles = (N_ALL + NTILE - 1) / NTILE;   // 1563 (last partial)

    float4 cpre[4], xpre[4];
    int tile = blockIdx.x;
    if (tile < ntiles) {
        #pragma unroll
        for (int j = 0; j < 4; j++) {
            int v = tile * NTILE + w * 8 + 2 * j + half;
            if (v < N_ALL) {
                cpre[j] = *(const float4*)&g_C[(size_t)v * DSZ + 4 * q];
                xpre[j] = ((const float4*)node_ptr(src_emb, dst_emb, v))[q];
            } else {
                cpre[j] = make_float4(0.f, 0.f, 0.f, 0.f);
                xpre[j] = make_float4(0.f, 0.f, 0.f, 0.f);
            }
        }
    }

    for (; tile < ntiles; tile += gridDim.x) {
        const int base = tile * NTILE;
        // phase A: store prefetched rows (xor-swizzled); zero-store consumed C
        #pragma unroll
        for (int j = 0; j < 4; j++) {
            int row = w * 8 + 2 * j + half;
            int v = base + row;
            float4 c4 = cpre[j], x4 = xpre[j];
            if (v < N_ALL)
                *(float4*)&g_C[(size_t)v * DSZ + 4 * q] = make_float4(0.f, 0.f, 0.f, 0.f);
            int off = row * SSTR + ((4 * q) ^ (row & 16));
            *(float2*)&sp1[off]     = make_float2(c4.x, c4.y);
            *(float2*)&sp1[off + 2] = make_float2(c4.z, c4.w);
            *(float2*)&sp2[off]     = make_float2(x4.x * c4.x, x4.y * c4.y);
            *(float2*)&sp2[off + 2] = make_float2(x4.z * c4.z, x4.w * c4.w);
        }
        __syncthreads();

        // prefetch NEXT tile's rows (overlaps the GEMM below)
        int nt = tile + gridDim.x;
        if (nt < ntiles) {
            #pragma unroll
            for (int j = 0; j < 4; j++) {
                int v = nt * NTILE + w * 8 + 2 * j + half;
                if (v < N_ALL) {
                    cpre[j] = *(const float4*)&g_C[(size_t)v * DSZ + 4 * q];
                    xpre[j] = ((const float4*)node_ptr(src_emb, dst_emb, v))[q];
                } else {
                    cpre[j] = make_float4(0.f, 0.f, 0.f, 0.f);
                    xpre[j] = make_float4(0.f, 0.f, 0.f, 0.f);
                }
            }
        }

        const int gvA = base + lane, gvB = base + lane + 32;
        const float c0A = (gvA < N_ALL) ? g_c0[gvA] : 0.f;
        const float c0B = (gvB < N_ALL) ? g_c0[gvB] : 0.f;

        f32x2_t acA[8], acB[8];
        #pragma unroll
        for (int o = 0; o < 8; o++) { acA[o] = 0; acB[o] = 0; }
        #pragma unroll 8
        for (int dp = 0; dp < 32; dp++) {
            const int poff = (2 * dp) ^ sA;
            f32x2_t p1A = *(const f32x2_t*)&sp1[pbA + poff];
            f32x2_t p2A = *(const f32x2_t*)&sp2[pbA + poff];
            f32x2_t p1B = *(const f32x2_t*)&sp1[pbB + poff];
            f32x2_t p2B = *(const f32x2_t*)&sp2[pbB + poff];
            const float* w1r = &sW1[dp * WSTR + wbase];   // broadcast: all lanes same addr
            const float* w2r = &sW2[dp * WSTR + wbase];
            ulonglong2 wA = *(const ulonglong2*)(w1r);
            ulonglong2 wB = *(const ulonglong2*)(w1r + 4);
            ulonglong2 wC = *(const ulonglong2*)(w1r + 8);
            ulonglong2 wD = *(const ulonglong2*)(w1r + 12);
            acA[0] = ffma2(p1A, wA.x, acA[0]); acB[0] = ffma2(p1B, wA.x, acB[0]);
            acA[1] = ffma2(p1A, wA.y, acA[1]); acB[1] = ffma2(p1B, wA.y, acB[1]);
            acA[2] = ffma2(p1A, wB.x, acA[2]); acB[2] = ffma2(p1B, wB.x, acB[2]);
            acA[3] = ffma2(p1A, wB.y, acA[3]); acB[3] = ffma2(p1B, wB.y, acB[3]);
            acA[4] = ffma2(p1A, wC.x, acA[4]); acB[4] = ffma2(p1B, wC.x, acB[4]);
            acA[5] = ffma2(p1A, wC.y, acA[5]); acB[5] = ffma2(p1B, wC.y, acB[5]);
            acA[6] = ffma2(p1A, wD.x, acA[6]); acB[6] = ffma2(p1B, wD.x, acB[6]);
            acA[7] = ffma2(p1A, wD.y, acA[7]); acB[7] = ffma2(p1B, wD.y, acB[7]);
            wA = *(const ulonglong2*)(w2r);
            wB = *(const ulonglong2*)(w2r + 4);
            wC = *(const ulonglong2*)(w2r + 8);
            wD = *(const ulonglong2*)(w2r + 12);
            acA[0] = ffma2(p2A, wA.x, acA[0]); acB[0] = ffma2(p2B, wA.x, acB[0]);
            acA[1] = ffma2(p2A, wA.y, acA[1]); acB[1] = ffma2(p2B, wA.y, acB[1]);
            acA[2] = ffma2(p2A, wB.x, acA[2]); acB[2] = ffma2(p2B, wB.x, acB[2]);
            acA[3] = ffma2(p2A, wB.y, acA[3]); acB[3] = ffma2(p2B, wB.y, acB[3]);
            acA[4] = ffma2(p2A, wC.x, acA[4]); acB[4] = ffma2(p2B, wC.x, acB[4]);
            acA[5] = ffma2(p2A, wC.y, acA[5]); acB[5] = ffma2(p2B, wC.y, acB[5]);
            acA[6] = ffma2(p2A, wD.x, acA[6]); acB[6] = ffma2(p2B, wD.x, acB[6]);
            acA[7] = ffma2(p2A, wD.y, acA[7]); acB[7] = ffma2(p2B, wD.y, acB[7]);
        }
        float va[8], vb[8];
        #pragma unroll
        for (int o = 0; o < 8; o++) {
            float lo, hi;
            unpack2(acA[o], lo, hi);
            float h = lo + hi + c0A * bias[o];
            va[o] = h > 0.f ? h : 0.2f * h;
            unpack2(acB[o], lo, hi);
            h = lo + hi + c0B * bias[o];
            vb[o] = h > 0.f ? h : 0.2f * h;
        }
        if (gvA < N_ALL) {
            *(float4*)&out[(size_t)gvA * DSZ + 8 * w]     = make_float4(va[0], va[1], va[2], va[3]);
            *(float4*)&out[(size_t)gvA * DSZ + 8 * w + 4] = make_float4(va[4], va[5], va[6], va[7]);
        }
        if (gvB < N_ALL) {
            *(float4*)&out[(size_t)gvB * DSZ + 8 * w]     = make_float4(vb[0], vb[1], vb[2], vb[3]);
            *(float4*)&out[(size_t)gvB * DSZ + 8 * w + 4] = make_float4(vb[4], vb[5], vb[6], vb[7]);
        }
        __syncthreads();   // all warps done reading c0/sp for this tile

        // zero c0 for this tile AFTER the barrier (no reader remains this launch;
        // next launch's edge_scatter is ordered by the kernel boundary)
        if (w == 0) {
            int z = base + 2 * lane;
            if (z + 1 < N_ALL) *(float2*)&g_c0[z] = make_float2(0.f, 0.f);
            else if (z < N_ALL) g_c0[z] = 0.f;
        }
    }
}

extern "C" void kernel_launch(void* const* d_in, const int* in_sizes, int n_in,
                              void* d_out, int out_size) {
    const float* src_emb = (const float*)d_in[0];
    const float* dst_emb = (const float*)d_in[1];
    const float* norm    = (const float*)d_in[2];
    const float* W1      = (const float*)d_in[3];
    const float* b1      = (const float*)d_in[4];
    const float* W2      = (const float*)d_in[5];
    const float* b2      = (const float*)d_in[6];
    const int*   esrc    = (const int*)d_in[7];
    const int*   edst    = (const int*)d_in[8];
    float* out = (float*)d_out;

    cudaFuncSetAttribute(node_final_kernel,
                         cudaFuncAttributeMaxDynamicSharedMemorySize, NF_SMEM);

    edge_scatter_kernel<<<1184, TPB>>>(src_emb, dst_emb, norm, esrc, edst, W1, W2);
    node_final_kernel<<<NF_GRID, TPB, NF_SMEM>>>(src_emb, dst_emb, b1, b2, out);
}